// round 1
// baseline (speedup 1.0000x reference)
#include <cuda_runtime.h>
#include <cuda_bf16.h>
#include <cstdint>
#include <cstddef>

// Problem constants
#define BB   4
#define NTOK 2048
#define DMODEL 1024
#define NH   16
#define HD   64
#define D3   (3 * DMODEL)      // 3072
#define MROWS (BB * NTOK)      // 8192
#define SCALE 0.125f           // 1/sqrt(64)

// Scratch (static device globals — allocation-free)
__device__ float g_qkv[(size_t)MROWS * D3];     // [B*N, 3*D] == [b,n,3,h,hd]
__device__ float g_att[(size_t)MROWS * DMODEL]; // [B*N, D]   attention output

// ---------------------------------------------------------------------------
// SGEMM: C[M,Nn] = A[M,K] @ W[K,Nn] + bias[Nn]
// BM=128, BN=64, BK=16; 256 threads; per-thread 8x4 micro-tile.
// ---------------------------------------------------------------------------
__global__ __launch_bounds__(256) void sgemm_bias_kernel(
    const float* __restrict__ A, const float* __restrict__ W,
    const float* __restrict__ bias, float* __restrict__ C,
    int M, int Nn, int K)
{
    __shared__ float As[16][128];
    __shared__ float Bs[16][64];

    const int t  = threadIdx.x;
    const int tx = t & 15;        // 0..15 -> cols tx*4 .. +3
    const int ty = t >> 4;        // 0..15 -> rows ty*8 .. +7
    const int m0 = blockIdx.y * 128;
    const int n0 = blockIdx.x * 64;

    float acc[8][4];
#pragma unroll
    for (int i = 0; i < 8; i++)
#pragma unroll
        for (int j = 0; j < 4; j++) acc[i][j] = 0.0f;

    // B tile load mapping: one float4 per thread
    const int brow = t >> 4;            // 0..15
    const int bc   = (t & 15) << 2;     // 0..60

    for (int k0 = 0; k0 < K; k0 += 16) {
        // Load A tile 128x16 -> As transposed [k][m]; 2 float4 per thread
#pragma unroll
        for (int i = 0; i < 2; i++) {
            int f4 = t * 2 + i;              // 0..511
            int row = f4 >> 2;               // 0..127
            int k4  = (f4 & 3) << 2;         // 0,4,8,12
            float4 a = *(const float4*)(A + (size_t)(m0 + row) * K + k0 + k4);
            As[k4 + 0][row] = a.x;
            As[k4 + 1][row] = a.y;
            As[k4 + 2][row] = a.z;
            As[k4 + 3][row] = a.w;
        }
        // Load B tile 16x64
        *(float4*)&Bs[brow][bc] =
            *(const float4*)(W + (size_t)(k0 + brow) * Nn + n0 + bc);
        __syncthreads();

#pragma unroll
        for (int kk = 0; kk < 16; kk++) {
            float4 a0 = *(const float4*)&As[kk][ty * 8 + 0];
            float4 a1 = *(const float4*)&As[kk][ty * 8 + 4];
            float4 bv = *(const float4*)&Bs[kk][tx * 4];
            float ar[8] = {a0.x, a0.y, a0.z, a0.w, a1.x, a1.y, a1.z, a1.w};
#pragma unroll
            for (int i = 0; i < 8; i++) {
                acc[i][0] += ar[i] * bv.x;
                acc[i][1] += ar[i] * bv.y;
                acc[i][2] += ar[i] * bv.z;
                acc[i][3] += ar[i] * bv.w;
            }
        }
        __syncthreads();
    }

    float4 bb = *(const float4*)(bias + n0 + tx * 4);
#pragma unroll
    for (int i = 0; i < 8; i++) {
        float4 o;
        o.x = acc[i][0] + bb.x;
        o.y = acc[i][1] + bb.y;
        o.z = acc[i][2] + bb.z;
        o.w = acc[i][3] + bb.w;
        *(float4*)(C + (size_t)(m0 + ty * 8 + i) * Nn + n0 + tx * 4) = o;
    }
}

// ---------------------------------------------------------------------------
// Flash attention: one CTA handles (b, h, 64 q-rows); streams K/V in 64-row
// tiles through shared memory with online softmax. All fp32.
// ---------------------------------------------------------------------------
#define APAD 68  // padded row stride (floats) for 64-wide tiles

__global__ __launch_bounds__(256) void attn_kernel(
    const float* __restrict__ qkv, float* __restrict__ out)
{
    extern __shared__ float sm[];
    float* Qs = sm;                 // [64][APAD]
    float* Ks = Qs + 64 * APAD;
    float* Vs = Ks + 64 * APAD;
    float* Ps = Vs + 64 * APAD;

    const int t  = threadIdx.x;
    const int q0 = blockIdx.x << 6;
    const int h  = blockIdx.y;
    const int b  = blockIdx.z;

    const size_t base = (size_t)b * NTOK * D3 + (size_t)h * HD;
    const float* Qg = qkv + base;                 // + n*D3 + d
    const float* Kg = qkv + base + DMODEL;
    const float* Vg = qkv + base + 2 * DMODEL;

    const int lr = t >> 4;          // 0..15
    const int lc = (t & 15) << 2;   // 0..60

    // Load Q tile (64 x 64)
#pragma unroll
    for (int p = 0; p < 4; p++) {
        int r = lr + (p << 4);
        *(float4*)(Qs + r * APAD + lc) =
            *(const float4*)(Qg + (size_t)(q0 + r) * D3 + lc);
    }

    const int tx = t & 15;   // k-col / hd-col group: cols tx*4 .. +3
    const int ty = t >> 4;   // q-row group: rows ty*4 .. +3

    float m[4], l[4], o[4][4];
#pragma unroll
    for (int i = 0; i < 4; i++) {
        m[i] = -1e30f; l[i] = 0.0f;
#pragma unroll
        for (int j = 0; j < 4; j++) o[i][j] = 0.0f;
    }

    for (int kt = 0; kt < NTOK / 64; kt++) {
        __syncthreads();  // previous iter's P/V reads done before overwrite
        const int k0 = kt << 6;
#pragma unroll
        for (int p = 0; p < 4; p++) {
            int r = lr + (p << 4);
            *(float4*)(Ks + r * APAD + lc) =
                *(const float4*)(Kg + (size_t)(k0 + r) * D3 + lc);
            *(float4*)(Vs + r * APAD + lc) =
                *(const float4*)(Vg + (size_t)(k0 + r) * D3 + lc);
        }
        __syncthreads();

        // S = Q @ K^T for 4x4 micro-tile
        float s[4][4];
#pragma unroll
        for (int i = 0; i < 4; i++)
#pragma unroll
            for (int j = 0; j < 4; j++) s[i][j] = 0.0f;

#pragma unroll 4
        for (int d = 0; d < HD; d += 4) {
            float4 qv[4], kv[4];
#pragma unroll
            for (int i = 0; i < 4; i++)
                qv[i] = *(const float4*)(Qs + (ty * 4 + i) * APAD + d);
#pragma unroll
            for (int j = 0; j < 4; j++)
                kv[j] = *(const float4*)(Ks + (tx * 4 + j) * APAD + d);
#pragma unroll
            for (int i = 0; i < 4; i++)
#pragma unroll
                for (int j = 0; j < 4; j++)
                    s[i][j] += qv[i].x * kv[j].x + qv[i].y * kv[j].y +
                               qv[i].z * kv[j].z + qv[i].w * kv[j].w;
        }

        // Online softmax per q-row (replicated across the 16 tx lanes)
#pragma unroll
        for (int i = 0; i < 4; i++) {
#pragma unroll
            for (int j = 0; j < 4; j++) s[i][j] *= SCALE;
            float mx = fmaxf(fmaxf(s[i][0], s[i][1]), fmaxf(s[i][2], s[i][3]));
#pragma unroll
            for (int off = 1; off < 16; off <<= 1)
                mx = fmaxf(mx, __shfl_xor_sync(0xffffffffu, mx, off));
            float mnew = fmaxf(m[i], mx);
            float corr = __expf(m[i] - mnew);
            float psum = 0.0f;
#pragma unroll
            for (int j = 0; j < 4; j++) {
                float p = __expf(s[i][j] - mnew);
                s[i][j] = p;
                psum += p;
            }
#pragma unroll
            for (int off = 1; off < 16; off <<= 1)
                psum += __shfl_xor_sync(0xffffffffu, psum, off);
            l[i] = l[i] * corr + psum;
            m[i] = mnew;
#pragma unroll
            for (int j = 0; j < 4; j++) o[i][j] *= corr;
            float4 pw = make_float4(s[i][0], s[i][1], s[i][2], s[i][3]);
            *(float4*)(Ps + (ty * 4 + i) * APAD + tx * 4) = pw;
        }
        __syncthreads();

        // O += P @ V for 4x4 micro-tile (cols = tx*4..+3 of hd)
#pragma unroll 4
        for (int k = 0; k < 64; k += 4) {
            float pr[4][4];
#pragma unroll
            for (int i = 0; i < 4; i++) {
                float4 pv = *(const float4*)(Ps + (ty * 4 + i) * APAD + k);
                pr[i][0] = pv.x; pr[i][1] = pv.y; pr[i][2] = pv.z; pr[i][3] = pv.w;
            }
#pragma unroll
            for (int kk = 0; kk < 4; kk++) {
                float4 vv = *(const float4*)(Vs + (k + kk) * APAD + (tx << 2));
#pragma unroll
                for (int i = 0; i < 4; i++) {
                    float p = pr[i][kk];
                    o[i][0] += p * vv.x;
                    o[i][1] += p * vv.y;
                    o[i][2] += p * vv.z;
                    o[i][3] += p * vv.w;
                }
            }
        }
    }

    // Normalize and write: out[b, q, h*64 + c]
#pragma unroll
    for (int i = 0; i < 4; i++) {
        float inv = 1.0f / l[i];
        float4 r;
        r.x = o[i][0] * inv;
        r.y = o[i][1] * inv;
        r.z = o[i][2] * inv;
        r.w = o[i][3] * inv;
        int q = q0 + ty * 4 + i;
        *(float4*)(out + ((size_t)(b * NTOK + q)) * DMODEL + h * HD + (tx << 2)) = r;
    }
}

// ---------------------------------------------------------------------------
// Launcher
// ---------------------------------------------------------------------------
extern "C" void kernel_launch(void* const* d_in, const int* in_sizes, int n_in,
                              void* d_out, int out_size)
{
    const float* x    = (const float*)d_in[0];
    const float* Wqkv = (const float*)d_in[1];
    const float* bqkv = (const float*)d_in[2];
    const float* Wout = (const float*)d_in[3];
    const float* bout = (const float*)d_in[4];
    float* out = (float*)d_out;

    float* qkv = nullptr;
    float* att = nullptr;
    cudaGetSymbolAddress((void**)&qkv, g_qkv);
    cudaGetSymbolAddress((void**)&att, g_att);

    const int attn_smem = 4 * 64 * APAD * (int)sizeof(float);  // 69632 B
    cudaFuncSetAttribute(attn_kernel,
                         cudaFuncAttributeMaxDynamicSharedMemorySize, attn_smem);

    // 1) QKV projection: [8192,1024] @ [1024,3072] + bias
    {
        dim3 grid(D3 / 64, MROWS / 128);
        sgemm_bias_kernel<<<grid, 256>>>(x, Wqkv, bqkv, qkv, MROWS, D3, DMODEL);
    }
    // 2) Attention
    {
        dim3 grid(NTOK / 64, NH, BB);
        attn_kernel<<<grid, 256, attn_smem>>>(qkv, att);
    }
    // 3) Output projection: [8192,1024] @ [1024,1024] + bias
    {
        dim3 grid(DMODEL / 64, MROWS / 128);
        sgemm_bias_kernel<<<grid, 256>>>(att, Wout, bout, out, MROWS, DMODEL, DMODEL);
    }
}